// round 12
// baseline (speedup 1.0000x reference)
#include <cuda_runtime.h>
#include <math.h>

// Sinkhorn approximate EMD: B=8, N=2048, 3D points, 50 iterations.
// R12: R11 skeleton (fused persistent kernel, 128 CTAs x 1024 thr, 16 CTAs
// per batch, 2 gpu-scope barriers/iter, single poller, packed ELL cutoff
// K>=1e-17, prefetch across barrier, multiplicative updates) MINUS the smem
// staging of the exchange vector: gathers read exp(u)/exp(v) directly from
// L2 via __ldcg (8 KB, L2-resident, MLP-hidden). Half 0 special-cased
// (exp(v0)=1 -> rowsum = sum of vals, no loads).

#define BB 8
#define NN 2048
#define NROWS (BB * NN)          // 16384
#define RSTRIDE 256              // padded max nnz per row (avg ~41, max ~150)
#define D2CUT 0.391510f          // ln(1e17)/100  -> K >= 1e-17
#define CPB 16                   // CTAs per batch
#define RPC 128                  // rows per CTA
#define TPB 1024                 // 128 groups x 8 lanes

__device__ unsigned g_pk[2][(size_t)NROWS * RSTRIDE];   // packed K / K^T (33.5 MB)
__device__ float    g_expu[NROWS], g_expv[NROWS];
__device__ float    g_part[BB * CPB];
__device__ unsigned g_bar[BB];   // zero at load; self-reset each call

__device__ __forceinline__ void bar_arrive(unsigned* p) {
    asm volatile("red.release.gpu.add.u32 [%0], 1;" :: "l"(p) : "memory");
}
__device__ __forceinline__ unsigned bar_peek(unsigned* p) {
    unsigned v;
    asm volatile("ld.acquire.gpu.u32 %0, [%1];" : "=r"(v) : "l"(p) : "memory");
    return v;
}

// dot of 4 packed entries against L2-resident vector (bypasses L1)
__device__ __forceinline__ float dotg(uint4 e, const float* __restrict__ vec) {
    float v0 = __ldcg(vec + (e.x & 0x7FFu));
    float v1 = __ldcg(vec + (e.y & 0x7FFu));
    float v2 = __ldcg(vec + (e.z & 0x7FFu));
    float v3 = __ldcg(vec + (e.w & 0x7FFu));
    return __uint_as_float(e.x & 0xFFFFF800u) * v0
         + __uint_as_float(e.y & 0xFFFFF800u) * v1
         + __uint_as_float(e.z & 0xFFFFF800u) * v2
         + __uint_as_float(e.w & 0xFFFFF800u) * v3;
}
__device__ __forceinline__ float sum4(uint4 e) {     // sev == 1 fast path
    return __uint_as_float(e.x & 0xFFFFF800u) + __uint_as_float(e.y & 0xFFFFF800u)
         + __uint_as_float(e.z & 0xFFFFF800u) + __uint_as_float(e.w & 0xFFFFF800u);
}

// ---------------------------------------------------------------------------
__global__ __launch_bounds__(TPB, 1)
void fused_sinkhorn(const float* __restrict__ x1, const float* __restrict__ x2,
                    float* __restrict__ out, float M) {
    __shared__ float sxbuf[NN * 3];          // build staging only
    __shared__ unsigned char sit[2][RPC];    // per-row 32-entry iteration counts
    __shared__ float red[32];

    int cta = blockIdx.x, batch = cta >> 4, crank = cta & (CPB - 1);
    int t = threadIdx.x, warp = t >> 5, lane = t & 31;
    int rowbase = batch * NN + crank * RPC;
    unsigned* barp = &g_bar[batch];
    unsigned target = 0;
    const float eps = 1e-8f;

    // ===== inline build: CTA-private packed-ELL rows of K and K^T =====
    #pragma unroll 1
    for (int m = 0; m < 2; ++m) {
        const float* rowpts = m ? x2 : x1;
        const float* colpts = m ? x1 : x2;
        const float* cp = colpts + (size_t)batch * NN * 3;
        for (int i = t; i < NN * 3; i += TPB) sxbuf[i] = cp[i];
        __syncthreads();

        #pragma unroll 1
        for (int rr = 0; rr < 4; ++rr) {             // 4 rows per warp (32 warps)
            int r   = warp * 4 + rr;
            int row = rowbase + r;
            const float* ap = rowpts + (size_t)row * 3;
            float ax = ap[0], ay = ap[1], az = ap[2];
            unsigned* krow = g_pk[m] + (size_t)row * RSTRIDE;

            unsigned base = 0;
            for (int c0 = 0; c0 < NN; c0 += 32) {
                int c = c0 + lane;
                float dx = ax - sxbuf[3 * c];
                float dy = ay - sxbuf[3 * c + 1];
                float dz = az - sxbuf[3 * c + 2];
                float d2 = fmaf(dx, dx, fmaf(dy, dy, dz * dz));
                bool p = d2 < D2CUT;
                unsigned mk = __ballot_sync(0xffffffffu, p);
                if (p) {
                    unsigned idx = base + __popc(mk & ((1u << lane) - 1u));
                    if (idx < RSTRIDE)   // RN-rounded 21-bit val | 11-bit col
                        krow[idx] = ((__float_as_uint(__expf(-100.0f * d2)) + 0x400u)
                                     & 0xFFFFF800u) | (unsigned)c;
                }
                base += __popc(mk);
            }
            unsigned nnz = (base < RSTRIDE) ? base : RSTRIDE;
            unsigned pad = (nnz + 31u) & ~31u;       // 32 entries per group-iter
            for (unsigned idx = nnz + lane; idx < pad; idx += 32) krow[idx] = 0u;
            if (lane == 0) sit[m][r] = (unsigned char)(pad >> 5);
        }
        __syncthreads();
    }

    // ===== 100 Sinkhorn half-iterations =====
    int g = t >> 3, gl = t & 7;                      // 128 groups x 8 lanes
    int myrow = rowbase + g;
    int itc0 = sit[0][g], itc1 = sit[1][g];
    const uint4* ep0 = (const uint4*)(g_pk[0] + (size_t)myrow * RSTRIDE) + gl;
    const uint4* ep1 = (const uint4*)(g_pk[1] + (size_t)myrow * RSTRIDE) + gl;
    float myeu = 0.0f;                               // leader: final exp(u)

    // prefetch half 0's first 64 entries (always in-bounds: 8 uint4 per lane)
    uint4 f0 = ep0[0];
    uint4 f1 = ep0[8];

    #pragma unroll 1
    for (int half = 0; half < 100; ++half) {
        int m = half & 1;   // 0: u update (K, reads expv); 1: v update (K^T, reads expu)
        int iters = m ? itc1 : itc0;
        const uint4* ep = m ? ep1 : ep0;
        const float* vec = (m ? g_expu : g_expv) + batch * NN;

        float acc;
        if (half == 0) {                             // exp(v0) = 1: pure val sum
            acc = sum4(f0);
            if (iters > 1) acc += sum4(f1);
            #pragma unroll 1
            for (int i = 2; i < iters; ++i) acc += sum4(ep[(size_t)i * 8]);
        } else {                                     // gather straight from L2
            acc = dotg(f0, vec);
            if (iters > 1) acc += dotg(f1, vec);
            #pragma unroll 1
            for (int i = 2; i < iters; ++i) acc += dotg(ep[(size_t)i * 8], vec);
        }

        acc += __shfl_xor_sync(0xffffffffu, acc, 4);
        acc += __shfl_xor_sync(0xffffffffu, acc, 2);
        acc += __shfl_xor_sync(0xffffffffu, acc, 1);

        if (gl == 0) {       // multiplicative update: exp(new) = M / (sum + eps)
            float ev = __fdividef(M, acc + eps);
            if (m == 0) myeu = ev;                   // half 98 leaves final exp(u)
            __stcg((m ? g_expv : g_expu) + myrow, ev);
        }

        // prefetch NEXT half's first 64 entries (matrix constant, no dependency)
        {
            const uint4* nep = m ? ep0 : ep1;
            f0 = nep[0];
            f1 = nep[8];
        }
        __syncthreads();                             // all stores issued before arrive

        target += CPB;
        if (t == 0) {
            bar_arrive(barp);
            while (bar_peek(barp) < target) { }      // single poller
        }
        __syncthreads();
    }

    // ===== epilogue: emd_b = -(1/100) sum_ij k ln(k) e^{u_i} e^{v_j} =====
    {
        const float* vec = g_expv + batch * NN;
        float racc = 0.0f;
        #pragma unroll 1
        for (int i = 0; i < itc0; ++i) {
            uint4 e = ep0[(size_t)i * 8];
            unsigned b;
            b = e.x & 0xFFFFF800u;
            if (b) { float k = __uint_as_float(b); racc += k * __logf(k) * __ldcg(vec + (e.x & 0x7FFu)); }
            b = e.y & 0xFFFFF800u;
            if (b) { float k = __uint_as_float(b); racc += k * __logf(k) * __ldcg(vec + (e.y & 0x7FFu)); }
            b = e.z & 0xFFFFF800u;
            if (b) { float k = __uint_as_float(b); racc += k * __logf(k) * __ldcg(vec + (e.z & 0x7FFu)); }
            b = e.w & 0xFFFFF800u;
            if (b) { float k = __uint_as_float(b); racc += k * __logf(k) * __ldcg(vec + (e.w & 0x7FFu)); }
        }
        racc += __shfl_xor_sync(0xffffffffu, racc, 4);
        racc += __shfl_xor_sync(0xffffffffu, racc, 2);
        racc += __shfl_xor_sync(0xffffffffu, racc, 1);

        float acc = (gl == 0) ? racc * myeu : 0.0f;  // leaders carry row sums
        #pragma unroll
        for (int o = 16; o; o >>= 1) acc += __shfl_down_sync(0xffffffffu, acc, o);
        if (lane == 0) red[warp] = acc;
        __syncthreads();
        if (warp == 0) {
            float s = red[lane];
            #pragma unroll
            for (int o = 16; o; o >>= 1) s += __shfl_down_sync(0xffffffffu, s, o);
            if (lane == 0) __stcg(&g_part[cta], s);
        }
    }
    __syncthreads();

    target += CPB;
    if (t == 0) {
        bar_arrive(barp);                 // release covers t0's g_part store
        if (crank == 0) {                 // only rank 0 waits; others exit
            while (bar_peek(barp) < target) { }
            float s = 0.0f;
            #pragma unroll
            for (int k = 0; k < CPB; ++k) s += __ldcg(&g_part[batch * CPB + k]);
            out[batch] = -s * 0.01f;      // cost = -ln(K)/100
            *barp = 0u;                   // reset for next graph replay
        }
    }
}

// ---------------------------------------------------------------------------
extern "C" void kernel_launch(void* const* d_in, const int* in_sizes, int n_in,
                              void* d_out, int out_size) {
    (void)in_sizes; (void)n_in; (void)out_size;
    const float* x1 = (const float*)d_in[0];
    const float* x2 = (const float*)d_in[1];
    float* out = (float*)d_out;

    const float M = 1.0f / 2048.0f + 1e-8f;   // exp(log(1/N + eps_log))
    fused_sinkhorn<<<BB * CPB, TPB>>>(x1, x2, out, M);
}

// round 13
// speedup vs baseline: 2.4023x; 2.4023x over previous
#include <cuda_runtime.h>
#include <math.h>

// Sinkhorn approximate EMD: B=8, N=2048, 3D points, 50 iterations.
// R13: R11 skeleton (fused persistent kernel, smem-staged exchange vector,
// LDS gathers, packed ELL cutoff K>=1e-17, prefetch across barrier,
// multiplicative updates) with 8 CTAs per batch (64 CTAs x 1024 thr,
// 256 rows/CTA, one row per 4-lane group) to halve barrier arrivals and
// scheduling spread. R12 lesson locked in: gathers go through LDS, never
// scattered LDG.

#define BB 8
#define NN 2048
#define NROWS (BB * NN)          // 16384
#define RSTRIDE 256              // padded max nnz per row (avg ~41, max ~150)
#define D2CUT 0.391510f          // ln(1e17)/100  -> K >= 1e-17
#define CPB 8                    // CTAs per batch
#define RPC 256                  // rows per CTA
#define TPB 1024                 // 256 groups x 4 lanes

__device__ unsigned g_pk[2][(size_t)NROWS * RSTRIDE];   // packed K / K^T (33.5 MB)
__device__ float    g_expu[NROWS], g_expv[NROWS];
__device__ float    g_part[BB * CPB];
__device__ unsigned g_bar[BB];   // zero at load; self-reset each call

__device__ __forceinline__ void bar_arrive(unsigned* p) {
    asm volatile("red.release.gpu.add.u32 [%0], 1;" :: "l"(p) : "memory");
}
__device__ __forceinline__ unsigned bar_peek(unsigned* p) {
    unsigned v;
    asm volatile("ld.acquire.gpu.u32 %0, [%1];" : "=r"(v) : "l"(p) : "memory");
    return v;
}

__device__ __forceinline__ float dot4(uint4 e, const float* sev) {
    return __uint_as_float(e.x & 0xFFFFF800u) * sev[e.x & 0x7FFu]
         + __uint_as_float(e.y & 0xFFFFF800u) * sev[e.y & 0x7FFu]
         + __uint_as_float(e.z & 0xFFFFF800u) * sev[e.z & 0x7FFu]
         + __uint_as_float(e.w & 0xFFFFF800u) * sev[e.w & 0x7FFu];
}

// ---------------------------------------------------------------------------
__global__ __launch_bounds__(TPB, 1)
void fused_sinkhorn(const float* __restrict__ x1, const float* __restrict__ x2,
                    float* __restrict__ out, float M) {
    __shared__ float sxbuf[NN * 3];          // build staging; first 2048 reused as sev
    __shared__ unsigned char sit[2][RPC];    // per-row 16-entry iteration counts
    __shared__ float red[32];
    float* sev = sxbuf;

    int cta = blockIdx.x, batch = cta >> 3, crank = cta & (CPB - 1);
    int t = threadIdx.x, warp = t >> 5, lane = t & 31;
    int rowbase = batch * NN + crank * RPC;
    unsigned* barp = &g_bar[batch];
    unsigned target = 0;
    const float eps = 1e-8f;

    // ===== inline build: CTA-private packed-ELL rows of K and K^T =====
    #pragma unroll 1
    for (int m = 0; m < 2; ++m) {
        const float* rowpts = m ? x2 : x1;
        const float* colpts = m ? x1 : x2;
        const float* cp = colpts + (size_t)batch * NN * 3;
        for (int i = t; i < NN * 3; i += TPB) sxbuf[i] = cp[i];
        __syncthreads();

        #pragma unroll 1
        for (int rr = 0; rr < 8; ++rr) {             // 8 rows per warp (32 warps)
            int r   = warp * 8 + rr;
            int row = rowbase + r;
            const float* ap = rowpts + (size_t)row * 3;
            float ax = ap[0], ay = ap[1], az = ap[2];
            unsigned* krow = g_pk[m] + (size_t)row * RSTRIDE;

            unsigned base = 0;
            for (int c0 = 0; c0 < NN; c0 += 32) {
                int c = c0 + lane;
                float dx = ax - sxbuf[3 * c];
                float dy = ay - sxbuf[3 * c + 1];
                float dz = az - sxbuf[3 * c + 2];
                float d2 = fmaf(dx, dx, fmaf(dy, dy, dz * dz));
                bool p = d2 < D2CUT;
                unsigned mk = __ballot_sync(0xffffffffu, p);
                if (p) {
                    unsigned idx = base + __popc(mk & ((1u << lane) - 1u));
                    if (idx < RSTRIDE)   // RN-rounded 21-bit val | 11-bit col
                        krow[idx] = ((__float_as_uint(__expf(-100.0f * d2)) + 0x400u)
                                     & 0xFFFFF800u) | (unsigned)c;
                }
                base += __popc(mk);
            }
            unsigned nnz = (base < RSTRIDE) ? base : RSTRIDE;
            unsigned pad = (nnz + 15u) & ~15u;       // 16 entries per group-iter
            for (unsigned idx = nnz + lane; idx < pad; idx += 32) krow[idx] = 0u;
            if (lane == 0) sit[m][r] = (unsigned char)(pad >> 4);
        }
        __syncthreads();
    }

    // ===== 100 Sinkhorn half-iterations =====
    int g = t >> 2, gl = t & 3;                      // 256 groups x 4 lanes
    int myrow = rowbase + g;
    int itc0 = sit[0][g], itc1 = sit[1][g];
    const uint4* ep0 = (const uint4*)(g_pk[0] + (size_t)myrow * RSTRIDE) + gl;
    const uint4* ep1 = (const uint4*)(g_pk[1] + (size_t)myrow * RSTRIDE) + gl;
    float myeu = 0.0f;                               // leader: final exp(u)

    // prefetch half 0's first 48 entries (in-bounds: RSTRIDE/4 = 64 uint4)
    uint4 f0 = ep0[0];
    uint4 f1 = ep0[4];
    uint4 f2 = ep0[8];

    #pragma unroll 1
    for (int half = 0; half < 100; ++half) {
        int m = half & 1;   // 0: u update (K, reads expv); 1: v update (K^T, reads expu)

        // stage source exp-vector (512 threads x float4)
        if (t < NN / 4) {
            ((float4*)sev)[t] = (half == 0)
                ? make_float4(1.f, 1.f, 1.f, 1.f)    // exp(v0) = 1
                : __ldcg((const float4*)((m ? g_expu : g_expv) + batch * NN) + t);
        }
        __syncthreads();

        int iters = m ? itc1 : itc0;
        const uint4* ep = m ? ep1 : ep0;

        float acc = dot4(f0, sev);                   // prefetched chunks
        if (iters > 1) acc += dot4(f1, sev);
        if (iters > 2) acc += dot4(f2, sev);
        #pragma unroll 1
        for (int i = 3; i < iters; ++i)              // rare tail (nnz > 48)
            acc += dot4(ep[(size_t)i * 4], sev);

        acc += __shfl_xor_sync(0xffffffffu, acc, 2);
        acc += __shfl_xor_sync(0xffffffffu, acc, 1);

        if (gl == 0) {       // multiplicative update: exp(new) = M / (sum + eps)
            float ev = __fdividef(M, acc + eps);
            if (m == 0) myeu = ev;                   // half 98 leaves final exp(u)
            __stcg((m ? g_expv : g_expu) + myrow, ev);
        }

        // prefetch NEXT half's first 48 entries (matrix constant — overlaps barrier)
        {
            const uint4* nep = m ? ep0 : ep1;
            f0 = nep[0];
            f1 = nep[4];
            f2 = nep[8];
        }
        __syncthreads();                             // all stores issued before arrive

        target += CPB;
        if (t == 0) {
            bar_arrive(barp);
            while (bar_peek(barp) < target) { }      // single poller
        }
        __syncthreads();
    }

    // ===== epilogue: emd_b = -(1/100) sum_ij k ln(k) e^{u_i} e^{v_j} =====
    if (t < NN / 4)
        ((float4*)sev)[t] = __ldcg((const float4*)(g_expv + batch * NN) + t);
    __syncthreads();

    float racc = 0.0f;
    #pragma unroll 1
    for (int i = 0; i < itc0; ++i) {
        uint4 e = ep0[(size_t)i * 4];
        unsigned b;
        b = e.x & 0xFFFFF800u;
        if (b) { float k = __uint_as_float(b); racc += k * __logf(k) * sev[e.x & 0x7FFu]; }
        b = e.y & 0xFFFFF800u;
        if (b) { float k = __uint_as_float(b); racc += k * __logf(k) * sev[e.y & 0x7FFu]; }
        b = e.z & 0xFFFFF800u;
        if (b) { float k = __uint_as_float(b); racc += k * __logf(k) * sev[e.z & 0x7FFu]; }
        b = e.w & 0xFFFFF800u;
        if (b) { float k = __uint_as_float(b); racc += k * __logf(k) * sev[e.w & 0x7FFu]; }
    }
    racc += __shfl_xor_sync(0xffffffffu, racc, 2);
    racc += __shfl_xor_sync(0xffffffffu, racc, 1);

    float acc = (gl == 0) ? racc * myeu : 0.0f;      // leaders carry row sums
    #pragma unroll
    for (int o = 16; o; o >>= 1) acc += __shfl_down_sync(0xffffffffu, acc, o);
    if (lane == 0) red[warp] = acc;
    __syncthreads();
    if (warp == 0) {
        float s = red[lane];
        #pragma unroll
        for (int o = 16; o; o >>= 1) s += __shfl_down_sync(0xffffffffu, s, o);
        if (lane == 0) __stcg(&g_part[cta], s);
    }
    __syncthreads();

    target += CPB;
    if (t == 0) {
        bar_arrive(barp);                 // release covers t0's g_part store
        if (crank == 0) {                 // only rank 0 waits; others exit
            while (bar_peek(barp) < target) { }
            float s = 0.0f;
            #pragma unroll
            for (int k = 0; k < CPB; ++k) s += __ldcg(&g_part[batch * CPB + k]);
            out[batch] = -s * 0.01f;      // cost = -ln(K)/100
            *barp = 0u;                   // reset for next graph replay
        }
    }
}

// ---------------------------------------------------------------------------
extern "C" void kernel_launch(void* const* d_in, const int* in_sizes, int n_in,
                              void* d_out, int out_size) {
    (void)in_sizes; (void)n_in; (void)out_size;
    const float* x1 = (const float*)d_in[0];
    const float* x2 = (const float*)d_in[1];
    float* out = (float*)d_out;

    const float M = 1.0f / 2048.0f + 1e-8f;   // exp(log(1/N + eps_log))
    fused_sinkhorn<<<BB * CPB, TPB>>>(x1, x2, out, M);
}

// round 14
// speedup vs baseline: 2.4882x; 1.0358x over previous
#include <cuda_runtime.h>
#include <math.h>

// Sinkhorn approximate EMD: B=8, N=2048, 3D points, 50 iterations.
// R14: R11 (full 128-CTA grid, smem-staged exchange, LDS gathers, packed
// ELL cutoff K>=1e-17, multiplicative updates) + R10's batch interleaving:
// batches paired (A=p, B=p+4), 32 CTAs per batch, 64 rows A + 64 rows B
// per CTA. The gpu-scope barrier of each batch propagates while the CTA
// computes the OTHER batch's chunk -> sync latency hidden at full grid.

#define BB 8
#define NN 2048
#define RSTRIDE 256              // padded max nnz per row (avg ~42, max ~80)
#define D2CUT 0.391510f          // ln(1e17)/100  -> K >= 1e-17
#define CPB 32                   // CTAs per batch
#define RPC 64                   // rows per CTA per batch
#define TPB 1024                 // 64 groups x 16 lanes
#define NCTA 128

__device__ unsigned g_pk[(size_t)NCTA * 4 * RPC * RSTRIDE];  // 4 slices/CTA (33.5 MB)
__device__ float    g_expu[BB * NN], g_expv[BB * NN];
__device__ float    g_part[BB * CPB];
__device__ unsigned g_bar[BB];   // zero at load; self-reset each call

__device__ __forceinline__ void bar_arrive(unsigned* p) {
    asm volatile("red.release.gpu.add.u32 [%0], 1;" :: "l"(p) : "memory");
}
__device__ __forceinline__ unsigned bar_peek(unsigned* p) {
    unsigned v;
    asm volatile("ld.acquire.gpu.u32 %0, [%1];" : "=r"(v) : "l"(p) : "memory");
    return v;
}

__device__ __forceinline__ float dot4(uint4 e, const float* sev) {
    return __uint_as_float(e.x & 0xFFFFF800u) * sev[e.x & 0x7FFu]
         + __uint_as_float(e.y & 0xFFFFF800u) * sev[e.y & 0x7FFu]
         + __uint_as_float(e.z & 0xFFFFF800u) * sev[e.z & 0x7FFu]
         + __uint_as_float(e.w & 0xFFFFF800u) * sev[e.w & 0x7FFu];
}

// ---------------------------------------------------------------------------
__global__ __launch_bounds__(TPB, 1)
void fused_sinkhorn(const float* __restrict__ x1, const float* __restrict__ x2,
                    float* __restrict__ out, float M) {
    __shared__ float pool[NN * 3];           // build pts; then sevA | sevB
    __shared__ unsigned char sit[4][RPC];    // per-slice per-row 64-entry iters
    __shared__ float red[32];
    float* sevA = pool;
    float* sevB = pool + NN;

    int cta = blockIdx.x, pairid = cta >> 5, crank = cta & 31;
    int bA = pairid, bB = pairid + 4;
    int t = threadIdx.x, warp = t >> 5, lane = t & 31;
    unsigned* barA = &g_bar[bA];
    unsigned* barB = &g_bar[bB];
    const float eps = 1e-8f;

    // ===== build 4 CTA-local ELL slices: sl = 2*pb + m (m=0:K, m=1:KT) =====
    #pragma unroll 1
    for (int sl = 0; sl < 4; ++sl) {
        int bat = (sl < 2) ? bA : bB;
        int m   = sl & 1;
        const float* rowpts = m ? x2 : x1;
        const float* colpts = m ? x1 : x2;
        const float* cp = colpts + (size_t)bat * NN * 3;
        for (int i = t; i < NN * 3; i += TPB) pool[i] = cp[i];
        __syncthreads();

        #pragma unroll 1
        for (int rr = 0; rr < 2; ++rr) {             // 2 rows per warp (32 warps)
            int r = warp * 2 + rr;
            const float* ap = rowpts + ((size_t)bat * NN + crank * RPC + r) * 3;
            float ax = ap[0], ay = ap[1], az = ap[2];
            unsigned* krow = g_pk + ((size_t)(cta * 4 + sl) * RPC + r) * RSTRIDE;

            unsigned base = 0;
            for (int c0 = 0; c0 < NN; c0 += 32) {
                int c = c0 + lane;
                float dx = ax - pool[3 * c];
                float dy = ay - pool[3 * c + 1];
                float dz = az - pool[3 * c + 2];
                float d2 = fmaf(dx, dx, fmaf(dy, dy, dz * dz));
                bool p = d2 < D2CUT;
                unsigned mk = __ballot_sync(0xffffffffu, p);
                if (p) {
                    unsigned idx = base + __popc(mk & ((1u << lane) - 1u));
                    if (idx < RSTRIDE)   // RN-rounded 21-bit val | 11-bit col
                        krow[idx] = ((__float_as_uint(__expf(-100.0f * d2)) + 0x400u)
                                     & 0xFFFFF800u) | (unsigned)c;
                }
                base += __popc(mk);
            }
            unsigned nnz = (base < RSTRIDE) ? base : RSTRIDE;
            unsigned pad = (nnz + 63u) & ~63u;       // 64 entries per group-iter
            if (pad == 0) pad = 64;
            for (unsigned idx = nnz + lane; idx < pad; idx += 32) krow[idx] = 0u;
            if (lane == 0) sit[sl][r] = (unsigned char)(pad >> 6);
        }
        __syncthreads();
    }

    // ===== main loop: 100 half-iterations, A/B interleaved barriers =====
    int g = t >> 4, gl = t & 15;                     // 64 groups x 16 lanes
    int rowA = bA * NN + crank * RPC + g;
    int rowB = bB * NN + crank * RPC + g;
    int itA0 = sit[0][g], itA1 = sit[1][g], itB0 = sit[2][g], itB1 = sit[3][g];
    const uint4* ePA0 = (const uint4*)(g_pk + ((size_t)(cta * 4 + 0) * RPC + g) * RSTRIDE) + gl;
    const uint4* ePA1 = (const uint4*)(g_pk + ((size_t)(cta * 4 + 1) * RPC + g) * RSTRIDE) + gl;
    const uint4* ePB0 = (const uint4*)(g_pk + ((size_t)(cta * 4 + 2) * RPC + g) * RSTRIDE) + gl;
    const uint4* ePB1 = (const uint4*)(g_pk + ((size_t)(cta * 4 + 3) * RPC + g) * RSTRIDE) + gl;
    float euA = 0.0f, euB = 0.0f;                    // leaders: final exp(u)
    unsigned tgtA = 0, tgtB = 0;

    uint4 f0 = ePA0[0];                              // prefetch half 0, chunk A

    #pragma unroll 1
    for (int half = 0; half < 100; ++half) {
        int m = half & 1;   // 0: u update (K, reads expv); 1: v update (KT, reads expu)

        // ---------- chunk A ----------
        if (half > 0) {
            if (t == 0) { while (bar_peek(barA) < tgtA) { } }
            __syncthreads();
            if (t < NN / 4)
                ((float4*)sevA)[t] =
                    __ldcg((const float4*)((m ? g_expu : g_expv) + bA * NN) + t);
        } else {
            if (t < NN / 4) ((float4*)sevA)[t] = make_float4(1.f, 1.f, 1.f, 1.f);
        }
        __syncthreads();
        {
            int iters = m ? itA1 : itA0;
            const uint4* ep = m ? ePA1 : ePA0;
            float acc = dot4(f0, sevA);
            #pragma unroll 1
            for (int i = 1; i < iters; ++i) acc += dot4(ep[(size_t)i * 16], sevA);
            acc += __shfl_xor_sync(0xffffffffu, acc, 8);
            acc += __shfl_xor_sync(0xffffffffu, acc, 4);
            acc += __shfl_xor_sync(0xffffffffu, acc, 2);
            acc += __shfl_xor_sync(0xffffffffu, acc, 1);
            if (gl == 0) {
                float ev = __fdividef(M, acc + eps);
                if (m == 0) euA = ev;                // half 98 leaves final exp(u)
                __stcg((m ? g_expv : g_expu) + rowA, ev);
            }
            f0 = (m ? ePB1 : ePB0)[0];               // prefetch chunk B
        }
        __syncthreads();
        if (t == 0) bar_arrive(barA);
        tgtA += CPB;

        // ---------- chunk B ----------
        if (half > 0) {
            if (t == 0) { while (bar_peek(barB) < tgtB) { } }
            __syncthreads();
            if (t < NN / 4)
                ((float4*)sevB)[t] =
                    __ldcg((const float4*)((m ? g_expu : g_expv) + bB * NN) + t);
        } else {
            if (t < NN / 4) ((float4*)sevB)[t] = make_float4(1.f, 1.f, 1.f, 1.f);
        }
        __syncthreads();
        {
            int iters = m ? itB1 : itB0;
            const uint4* ep = m ? ePB1 : ePB0;
            float acc = dot4(f0, sevB);
            #pragma unroll 1
            for (int i = 1; i < iters; ++i) acc += dot4(ep[(size_t)i * 16], sevB);
            acc += __shfl_xor_sync(0xffffffffu, acc, 8);
            acc += __shfl_xor_sync(0xffffffffu, acc, 4);
            acc += __shfl_xor_sync(0xffffffffu, acc, 2);
            acc += __shfl_xor_sync(0xffffffffu, acc, 1);
            if (gl == 0) {
                float ev = __fdividef(M, acc + eps);
                if (m == 0) euB = ev;
                __stcg((m ? g_expv : g_expu) + rowB, ev);
            }
            f0 = (m ? ePA0 : ePA1)[0];               // prefetch next half, chunk A
        }
        __syncthreads();
        if (t == 0) bar_arrive(barB);
        tgtB += CPB;
    }

    // ===== epilogue: emd_b = -(1/100) sum_ij k ln(k) e^{u_i} e^{v_j} =====
    #pragma unroll 1
    for (int pb = 0; pb < 2; ++pb) {
        int bat = pb ? bB : bA;
        float* sev = pb ? sevB : sevA;
        unsigned* barp = pb ? barB : barA;
        unsigned tgt = pb ? tgtB : tgtA;
        int iters = pb ? itB0 : itA0;
        const uint4* ep = pb ? ePB0 : ePA0;
        float eu = pb ? euB : euA;

        if (t == 0) { while (bar_peek(barp) < tgt) { } }
        __syncthreads();
        if (t < NN / 4)
            ((float4*)sev)[t] = __ldcg((const float4*)(g_expv + bat * NN) + t);
        __syncthreads();

        float racc = 0.0f;
        #pragma unroll 1
        for (int i = 0; i < iters; ++i) {
            uint4 e = ep[(size_t)i * 16];
            unsigned b;
            b = e.x & 0xFFFFF800u;
            if (b) { float k = __uint_as_float(b); racc += k * __logf(k) * sev[e.x & 0x7FFu]; }
            b = e.y & 0xFFFFF800u;
            if (b) { float k = __uint_as_float(b); racc += k * __logf(k) * sev[e.y & 0x7FFu]; }
            b = e.z & 0xFFFFF800u;
            if (b) { float k = __uint_as_float(b); racc += k * __logf(k) * sev[e.z & 0x7FFu]; }
            b = e.w & 0xFFFFF800u;
            if (b) { float k = __uint_as_float(b); racc += k * __logf(k) * sev[e.w & 0x7FFu]; }
        }
        racc += __shfl_xor_sync(0xffffffffu, racc, 8);
        racc += __shfl_xor_sync(0xffffffffu, racc, 4);
        racc += __shfl_xor_sync(0xffffffffu, racc, 2);
        racc += __shfl_xor_sync(0xffffffffu, racc, 1);

        float acc = (gl == 0) ? racc * eu : 0.0f;    // leaders carry row sums
        #pragma unroll
        for (int o = 16; o; o >>= 1) acc += __shfl_down_sync(0xffffffffu, acc, o);
        if (lane == 0) red[warp] = acc;
        __syncthreads();
        if (warp == 0) {
            float s = red[lane];
            #pragma unroll
            for (int o = 16; o; o >>= 1) s += __shfl_down_sync(0xffffffffu, s, o);
            if (lane == 0) __stcg(&g_part[bat * CPB + crank], s);
        }
        __syncthreads();
        if (t == 0) bar_arrive(barp);
        if (pb) tgtB += CPB; else tgtA += CPB;
    }

    // designated CTA (crank 0) finalizes both batches of its pair
    if (crank == 0 && t == 0) {
        while (bar_peek(barA) < tgtA) { }
        float s = 0.0f;
        #pragma unroll
        for (int k = 0; k < CPB; ++k) s += __ldcg(&g_part[bA * CPB + k]);
        out[bA] = -s * 0.01f;            // cost = -ln(K)/100
        *barA = 0u;                      // reset for next graph replay
        while (bar_peek(barB) < tgtB) { }
        s = 0.0f;
        #pragma unroll
        for (int k = 0; k < CPB; ++k) s += __ldcg(&g_part[bB * CPB + k]);
        out[bB] = -s * 0.01f;
        *barB = 0u;
    }
}

// ---------------------------------------------------------------------------
extern "C" void kernel_launch(void* const* d_in, const int* in_sizes, int n_in,
                              void* d_out, int out_size) {
    (void)in_sizes; (void)n_in; (void)out_size;
    const float* x1 = (const float*)d_in[0];
    const float* x2 = (const float*)d_in[1];
    float* out = (float*)d_out;

    const float M = 1.0f / 2048.0f + 1e-8f;   // exp(log(1/N + eps_log))
    fused_sinkhorn<<<NCTA, TPB>>>(x1, x2, out, M);
}